// round 15
// baseline (speedup 1.0000x reference)
#include <cuda_runtime.h>
#include <cuda.h>
#include <cuda_bf16.h>
#include <cuda_fp16.h>
#include <cstdint>

// Problem constants
#define Bb 32
#define Tt 2000
#define DIN 512
#define HH 512
#define MM (Bb * Tt)            // 64000 rows
#define NCHUNK 40
#define LCHUNK 50               // Tt / NCHUNK
#define NSTAT (NCHUNK * Bb)     // 1280 stats partials
#define NRED 160                // second-level stats partials

#define ALPHA_LO 0.8187307530779818f   // exp(-1/5)
#define ALPHA_HI 0.9607894391523232f   // exp(-1/25)
#define BN_EPS 1e-5f

// tcgen05/TMA-cg2 are only legal on the arch-specific (sm_103a) pass.
#if defined(__CUDA_ARCH__) && (defined(__CUDA_ARCH_FEAT_SM103_ALL) || \
    defined(__CUDA_ARCH_FEAT_SM100_ALL) || defined(__CUDA_ARCH_SPECIFIC__) || \
    defined(__CUDA_ARCH_FAMILY_SPECIFIC__))
#define TC_OK 1
#else
#define TC_OK 0
#endif

// ---------------- scratch (device globals; no allocation allowed) ----------
__device__ __align__(16) __half g_Wx[(size_t)MM * HH];  // 65.5 MB (fp16)
__device__ __align__(16) __nv_bfloat16 g_Whi[(size_t)HH * DIN];
__device__ __align__(16) __nv_bfloat16 g_Wlo[(size_t)HH * DIN];
__device__ float g_part_sum[NSTAT * HH];
__device__ float g_part_sq[NSTAT * HH];
__device__ float g_red_sum[NRED * HH];
__device__ float g_red_sq[NRED * HH];
__device__ float g_pa[HH], g_poma[HH], g_pg[HH], g_pc[HH], g_paL[HH];
__device__ float g_chunkend[(size_t)NCHUNK * Bb * HH];   // RAW (pre-BN) endpoints
__device__ float g_start[(size_t)NCHUNK * Bb * HH];
__device__ float g_accpart[(size_t)NCHUNK * Bb * HH];

// ======================= PTX helpers (arch-guarded) ========================
__device__ __forceinline__ uint32_t smem_u32(const void* p) {
    uint32_t a;
    asm("{ .reg .u64 t; cvta.to.shared.u64 t, %1; cvt.u32.u64 %0, t; }" : "=r"(a) : "l"(p));
    return a;
}
__device__ __forceinline__ uint32_t elect_one() {
    uint32_t pred;
    asm volatile("{\n\t.reg .pred p;\n\telect.sync _|p, 0xFFFFFFFF;\n\tselp.b32 %0, 1, 0, p;\n\t}" : "=r"(pred));
    return pred;
}
__device__ __forceinline__ uint32_t cl_rank() {
    uint32_t r;
    asm("mov.u32 %0, %%cluster_ctarank;" : "=r"(r));
    return r;
}
__device__ __forceinline__ void cluster_sync() {
    asm volatile("barrier.cluster.arrive.aligned;" ::: "memory");
    asm volatile("barrier.cluster.wait.aligned;" ::: "memory");
}
__device__ __forceinline__ void mbar_init(uint32_t a, uint32_t n) {
    asm volatile("mbarrier.init.shared.b64 [%0], %1;" :: "r"(a), "r"(n) : "memory");
}
__device__ __forceinline__ void mbar_arrive_local(uint32_t a) {
    asm volatile("mbarrier.arrive.shared.b64 _, [%0];" :: "r"(a) : "memory");
}
__device__ __forceinline__ void mbar_expect_tx(uint32_t a, uint32_t bytes) {
    asm volatile("mbarrier.arrive.expect_tx.shared.b64 _, [%0], %1;"
                 :: "r"(a), "r"(bytes) : "memory");
}
// local wait (acquire cta)
__device__ __forceinline__ void mbar_wait(uint32_t a, uint32_t parity) {
    asm volatile(
        "{\n\t.reg .pred P;\n\t"
        "LW%=:\n\t"
        "mbarrier.try_wait.parity.acquire.cta.shared::cta.b64 P, [%0], %1, 0x989680;\n\t"
        "@P bra LD%=;\n\t"
        "bra LW%=;\n\t"
        "LD%=:\n\t}"
        :: "r"(a), "r"(parity) : "memory");
}
// cluster-scope acquire wait
__device__ __forceinline__ void mbar_wait_cl(uint32_t a, uint32_t parity) {
    asm volatile(
        "{\n\t.reg .pred P;\n\t"
        "LW%=:\n\t"
        "mbarrier.try_wait.parity.acquire.cluster.shared::cta.b64 P, [%0], %1, 0x989680;\n\t"
        "@P bra LD%=;\n\t"
        "bra LW%=;\n\t"
        "LD%=:\n\t}"
        :: "r"(a), "r"(parity) : "memory");
}
// arrive (release, cluster scope) on target-rank CTA's mbarrier at same offset
__device__ __forceinline__ void mbar_arrive_rank(uint32_t local_mbar, uint32_t tgt) {
    asm volatile(
        "{\n\t.reg .b32 ra;\n\t"
        "mapa.shared::cluster.u32 ra, %0, %1;\n\t"
        "mbarrier.arrive.release.cluster.shared::cluster.b64 _, [ra];\n\t}"
        :: "r"(local_mbar), "r"(tgt) : "memory");
}
__device__ __forceinline__ void tc_alloc_cg2(uint32_t smem_addr, uint32_t ncols) {
#if TC_OK
    asm volatile("tcgen05.alloc.cta_group::2.sync.aligned.shared::cta.b32 [%0], %1;"
                 :: "r"(smem_addr), "r"(ncols) : "memory");
#endif
}
__device__ __forceinline__ void tc_relinq_cg2() {
#if TC_OK
    asm volatile("tcgen05.relinquish_alloc_permit.cta_group::2.sync.aligned;");
#endif
}
__device__ __forceinline__ void tc_dealloc_cg2(uint32_t tmem, uint32_t ncols) {
#if TC_OK
    asm volatile("tcgen05.dealloc.cta_group::2.sync.aligned.b32 %0, %1;" :: "r"(tmem), "r"(ncols));
#endif
}
__device__ __forceinline__ void tc_commit_mc2(uint32_t mbar, uint16_t mask) {
#if TC_OK
    asm volatile(
        "tcgen05.commit.cta_group::2.mbarrier::arrive::one.shared::cluster.multicast::cluster.b64 [%0], %1;"
        :: "r"(mbar), "h"(mask) : "memory");
#endif
}
__device__ __forceinline__ void fence_async_smem() {
    asm volatile("fence.proxy.async.shared::cta;" ::: "memory");
}
__device__ __forceinline__ void tc_fence_after() {
#if TC_OK
    asm volatile("tcgen05.fence::after_thread_sync;" ::: "memory");
#endif
}
__device__ __forceinline__ void tc_wait_ld() {
#if TC_OK
    asm volatile("tcgen05.wait::ld.sync.aligned;" ::: "memory");
#endif
}
// cg2 bf16 SS MMA (M=256 across the pair)
__device__ __forceinline__ void mma_f16_ss_cg2(uint32_t d, uint64_t ad, uint64_t bd,
                                               uint32_t idesc, uint32_t en) {
#if TC_OK
    asm volatile(
        "{\n\t.reg .pred p;\n\tsetp.ne.u32 p, %5, 0;\n\t"
        "tcgen05.mma.cta_group::2.kind::f16 [%0], %1, %2, %3, {%4,%4,%4,%4,%4,%4,%4,%4}, p;\n\t}"
        :: "r"(d), "l"(ad), "l"(bd), "r"(idesc), "r"(0u), "r"(en) : "memory");
#endif
}
// cg2 TMA: data -> local smem, complete_tx -> leader CTA's barrier (bit24 clear)
__device__ __forceinline__ void tma_b_cg2(uint32_t smem_dst, const CUtensorMap* map,
                                          int cx, int cy, uint32_t mbar) {
#if TC_OK
    asm volatile(
        "{\n\t.reg .b32 lb;\n\t"
        "and.b32 lb, %5, 0xFEFFFFFF;\n\t"
        "cp.async.bulk.tensor.3d.cta_group::2.shared::cluster.global.tile.mbarrier::complete_tx::bytes "
        "[%0], [%1, {%2, %3, %4}], [lb];\n\t}"
        :: "r"(smem_dst), "l"(map), "r"(cx), "r"(cy), "r"(0), "r"(mbar) : "memory");
#endif
}
__device__ __forceinline__ void ldtm_x32(uint32_t* r, uint32_t addr) {
#if TC_OK
    asm volatile(
        "tcgen05.ld.sync.aligned.32x32b.x32.b32 "
        "{%0, %1, %2, %3, %4, %5, %6, %7, %8, %9, %10, %11, %12, %13, %14, %15, "
        " %16, %17, %18, %19, %20, %21, %22, %23, %24, %25, %26, %27, %28, %29, %30, %31}, [%32];"
        : "=r"(r[0]), "=r"(r[1]), "=r"(r[2]), "=r"(r[3]), "=r"(r[4]), "=r"(r[5]), "=r"(r[6]), "=r"(r[7]),
          "=r"(r[8]), "=r"(r[9]), "=r"(r[10]), "=r"(r[11]), "=r"(r[12]), "=r"(r[13]), "=r"(r[14]), "=r"(r[15]),
          "=r"(r[16]), "=r"(r[17]), "=r"(r[18]), "=r"(r[19]), "=r"(r[20]), "=r"(r[21]), "=r"(r[22]), "=r"(r[23]),
          "=r"(r[24]), "=r"(r[25]), "=r"(r[26]), "=r"(r[27]), "=r"(r[28]), "=r"(r[29]), "=r"(r[30]), "=r"(r[31])
        : "r"(addr));
#else
    for (int i = 0; i < 32; i++) r[i] = 0u;
#endif
}
#define SMEM_DESC_BASE_SW128 \
    ((uint64_t(2) << 61) | (uint64_t(1) << 46) | (uint64_t(64) << 32) | (uint64_t(1) << 16))
__device__ __forceinline__ uint64_t make_desc(uint32_t addr) {
    return SMEM_DESC_BASE_SW128 | ((uint64_t)(addr >> 4) & 0x3FFF);
}

// fp32 pair -> packed bf16x2 hi, residual packed bf16x2 lo
__device__ __forceinline__ uint32_t bf2_hi_lo(float a, float b, uint32_t& lo) {
    uint32_t hi;
    asm("cvt.rn.bf16x2.f32 %0, %1, %2;" : "=r"(hi) : "f"(b), "f"(a));
    __nv_bfloat162 h = *(__nv_bfloat162*)&hi;
    float ra = a - __bfloat162float(h.x);
    float rb = b - __bfloat162float(h.y);
    asm("cvt.rn.bf16x2.f32 %0, %1, %2;" : "=r"(lo) : "f"(rb), "f"(ra));
    return hi;
}
// 4 halves -> float4
__device__ __forceinline__ float4 h4_to_f4(uint2 v) {
    float2 f01 = __half22float2(*(__half2*)&v.x);
    float2 f23 = __half22float2(*(__half2*)&v.y);
    return make_float4(f01.x, f01.y, f23.x, f23.y);
}

// ---------------- dummy (ncu launch-index alignment) -----------------------
__global__ void dummy_k() {}

// ---------------- W -> bf16 hi/lo (tiny, once) -----------------------------
__global__ void convert_W(const float* __restrict__ W) {
    size_t i = ((size_t)blockIdx.x * 256 + threadIdx.x) * 4;
    float4 v = *(const float4*)(W + i);
    uint32_t l01, l23;
    uint32_t h01 = bf2_hi_lo(v.x, v.y, l01);
    uint32_t h23 = bf2_hi_lo(v.z, v.w, l23);
    *(uint2*)((uint16_t*)g_Whi + i) = make_uint2(h01, h23);
    *(uint2*)((uint16_t*)g_Wlo + i) = make_uint2(l01, l23);
}

// ======================= tcgen05 cg2 GEMM: TMA B + A loaders ===============
// Cluster of 2 CTAs = one M=256 x N=256 tile; TMEM 256 cols/CTA, 2 clusters
// co-resident per SM pair. Grid 1000 CTAs = 500 clusters.
// Per chunk j (K=64): sub0 = Bhi (slot0), sub1 = Blo (slot1). B via cg2 TMA
// (HW completion to leader's BF barriers); A via 8 loader warps (fp32->hi/lo).
// Warps: 0-7 A loaders, 8 B-TMA issuer (both ranks), 9 MMA (rank 0).
#define BK 64
// smem barrier offsets
#define SM_AE 8u                 // A_empty[2]
#define SM_AF 24u                // A_full[2]  (leader)
#define SM_BE 40u                // B_empty[2]
#define SM_BF 56u                // B_full[2]  (leader, TMA tx)
#define SM_DONE 72u
#define SM_A0 1024u
#define SM_A1 33792u
#define SM_B0 66560u
#define SM_B1 82944u
#define SM_TOTAL 99328
// idesc: dtype=F32, atype=BF16, btype=BF16, N=256, M=256 (cg2)
#define GEMM_IDESC ((1u << 4) | (1u << 7) | (1u << 10) | (32u << 17) | (16u << 24))

__global__ __launch_bounds__(320, 2) __cluster_dims__(2, 1, 1)
void gemm_tc(const float* __restrict__ xa, const float* __restrict__ bias,
             const __grid_constant__ CUtensorMap mapHi,
             const __grid_constant__ CUtensorMap mapLo)
{
    extern __shared__ char smem[];
    const uint32_t sb = smem_u32(smem);
    const int tid = threadIdx.x;
    const int wid = tid >> 5;
    const int lid = tid & 31;
    const uint32_t rank = cl_rank();
    const int clus = blockIdx.x >> 1;
    const int N0 = (clus & 1) * 256;                     // cluster's N half
    const int mA = (clus >> 1) * 256 + (int)rank * 128;  // this CTA's 128 A rows
    const int nB = N0 + (int)rank * 128;                 // this CTA's 128 B rows

    if (wid == 8) {
        tc_alloc_cg2(sb + 0, 256);
        tc_relinq_cg2();
    }
    if (tid == 0) {
        for (int s = 0; s < 2; s++) { mbar_init(sb + SM_AE + s * 8, 1); mbar_arrive_local(sb + SM_AE + s * 8); }
        for (int s = 0; s < 2; s++) { mbar_init(sb + SM_AF + s * 8, 2); }
        for (int s = 0; s < 2; s++) { mbar_init(sb + SM_BE + s * 8, 1); mbar_arrive_local(sb + SM_BE + s * 8); }
        for (int s = 0; s < 2; s++) { mbar_init(sb + SM_BF + s * 8, 1); }
        mbar_init(sb + SM_DONE, 1);
    }
    __syncthreads();
    cluster_sync();                   // barriers visible cluster-wide
    uint32_t tbase;
    asm volatile("ld.shared.b32 %0, [%1];" : "=r"(tbase) : "r"(sb + 0));

    // A loader: own 128 rows x 64 cols fp32 -> hi(16K)+lo(16K) SW128
    auto load_a = [&](int k0, char* abuf) {
#pragma unroll
        for (int i2 = 0; i2 < 4; i2++) {
            int idx = i2 * 256 + tid;           // 0..1023
            int row = idx >> 3, u = idx & 7;
            const float* s = xa + (size_t)(mA + row) * DIN + k0 + u * 8;
            float4 f0 = *(const float4*)s;
            float4 f1 = *(const float4*)(s + 4);
            uint32_t l0, l1, l2, l3;
            uint4 hv;
            hv.x = bf2_hi_lo(f0.x, f0.y, l0);
            hv.y = bf2_hi_lo(f0.z, f0.w, l1);
            hv.z = bf2_hi_lo(f1.x, f1.y, l2);
            hv.w = bf2_hi_lo(f1.z, f1.w, l3);
            int off = row * 128 + ((u ^ (row & 7)) * 16);
            *(uint4*)(abuf + off) = hv;
            *(uint4*)(abuf + off + 16384) = make_uint4(l0, l1, l2, l3);
        }
    };

    if (tid < 256) {
        // ---- A loader warps: once per chunk ----
        for (int j = 0; j < 8; j++) {
#if TC_OK
            mbar_wait(sb + SM_AE + (j & 1) * 8, (j >> 1) & 1);
#endif
            load_a(j * BK, smem + ((j & 1) ? SM_A1 : SM_A0));
            fence_async_smem();
            asm volatile("bar.sync 1, 256;" ::: "memory");
            if (tid == 0) mbar_arrive_rank(sb + SM_AF + (j & 1) * 8, 0);
        }
    } else if (wid == 8) {
        // ---- B TMA issuer (both ranks; one elected lane issues) ----
        uint32_t el = elect_one();
        for (int j = 0; j < 8; j++) {
#if TC_OK
            mbar_wait(sb + SM_BE + 0 * 8, j & 1);
            if (el) {
                if (rank == 0) mbar_expect_tx(sb + SM_BF + 0 * 8, 32768u);
                tma_b_cg2(sb + SM_B0, &mapHi, j * BK, nB, sb + SM_BF + 0 * 8);
            }
            mbar_wait(sb + SM_BE + 1 * 8, j & 1);
            if (el) {
                if (rank == 0) mbar_expect_tx(sb + SM_BF + 1 * 8, 32768u);
                tma_b_cg2(sb + SM_B1, &mapLo, j * BK, nB, sb + SM_BF + 1 * 8);
            }
#endif
        }
    } else if (rank == 0) {
        // ---- MMA warp (warp 9, leader CTA; one elected lane issues) ----
        uint32_t el = elect_one();
        for (int j = 0; j < 8; j++) {
#if TC_OK
            mbar_wait_cl(sb + SM_AF + (j & 1) * 8, (j >> 1) & 1);
#endif
            uint32_t abase = sb + ((j & 1) ? SM_A1 : SM_A0);
            uint64_t adh = make_desc(abase);
            uint64_t adl = make_desc(abase + 16384u);
#if TC_OK
            mbar_wait_cl(sb + SM_BF + 0 * 8, j & 1);
#endif
            if (el) {
                uint64_t bd = make_desc(sb + SM_B0);
#pragma unroll
                for (int ks = 0; ks < 4; ks++) {
                    uint32_t en = (j == 0 && ks == 0) ? 0u : 1u;
                    mma_f16_ss_cg2(tbase, adh + ks * 2, bd + ks * 2, GEMM_IDESC, en);
                    mma_f16_ss_cg2(tbase, adl + ks * 2, bd + ks * 2, GEMM_IDESC, 1u);
                }
                tc_commit_mc2(sb + SM_BE + 0 * 8, 0x3);
            }
#if TC_OK
            mbar_wait_cl(sb + SM_BF + 1 * 8, j & 1);
#endif
            if (el) {
                uint64_t bd = make_desc(sb + SM_B1);
#pragma unroll
                for (int ks = 0; ks < 4; ks++)
                    mma_f16_ss_cg2(tbase, adh + ks * 2, bd + ks * 2, GEMM_IDESC, 1u);
                tc_commit_mc2(sb + SM_BE + 1 * 8, 0x3);
                tc_commit_mc2(sb + SM_AE + (j & 1) * 8, 0x3);
            }
        }
        if (el) tc_commit_mc2(sb + SM_DONE, 0x3);   // all MMAs complete -> DONE
    }

    // ---- drain: every thread waits DONE (multicast to both CTAs) ----
#if TC_OK
    mbar_wait(sb + SM_DONE, 0);
#endif
    __syncthreads();
    tc_fence_after();

    // epilogue: each CTA reads its own 128 TMEM lanes x 256 cols -> fp16 out
    if (wid < 8) {
        const int half = wid >> 2;             // col half
        const int m = mA + (wid & 3) * 32 + lid;
        __half* dst = g_Wx + (size_t)m * HH + N0 + half * 128;
#pragma unroll 1
        for (int c0 = 0; c0 < 128; c0 += 32) {
            uint32_t r[32];
            ldtm_x32(r, tbase + half * 128 + c0);
            tc_wait_ld();
#pragma unroll
            for (int jj = 0; jj < 32; jj += 8) {
                float4 bv0 = *(const float4*)(bias + N0 + half * 128 + c0 + jj);
                float4 bv1 = *(const float4*)(bias + N0 + half * 128 + c0 + jj + 4);
                __half2 h0 = __floats2half2_rn(__uint_as_float(r[jj + 0]) + bv0.x,
                                               __uint_as_float(r[jj + 1]) + bv0.y);
                __half2 h1 = __floats2half2_rn(__uint_as_float(r[jj + 2]) + bv0.z,
                                               __uint_as_float(r[jj + 3]) + bv0.w);
                __half2 h2 = __floats2half2_rn(__uint_as_float(r[jj + 4]) + bv1.x,
                                               __uint_as_float(r[jj + 5]) + bv1.y);
                __half2 h3 = __floats2half2_rn(__uint_as_float(r[jj + 6]) + bv1.z,
                                               __uint_as_float(r[jj + 7]) + bv1.w);
                uint4 o;
                o.x = *(uint32_t*)&h0; o.y = *(uint32_t*)&h1;
                o.z = *(uint32_t*)&h2; o.w = *(uint32_t*)&h3;
                *(uint4*)(dst + c0 + jj) = o;
            }
        }
    }
    __syncthreads();
    if (wid == 8) {
        tc_dealloc_cg2(tbase, 256);
    }
    cluster_sync();         // no CTA exits while peer ops may be in flight
}

// ---------------- Fused: chunk carries (raw) + BN stat partials ------------
__global__ __launch_bounds__(128)
void carry_stats(const float* __restrict__ alpha)
{
    const int k = blockIdx.x, b = blockIdx.y, tid = threadIdx.x;
    const int h4 = tid * 4;
    float4 av = *(const float4*)(alpha + h4);
    float4 a;
    a.x = fminf(fmaxf(av.x, ALPHA_LO), ALPHA_HI);
    a.y = fminf(fmaxf(av.y, ALPHA_LO), ALPHA_HI);
    a.z = fminf(fmaxf(av.z, ALPHA_LO), ALPHA_HI);
    a.w = fminf(fmaxf(av.w, ALPHA_LO), ALPHA_HI);
    float4 oma = {1.f - a.x, 1.f - a.y, 1.f - a.z, 1.f - a.w};
    float4 ut = {0.f, 0.f, 0.f, 0.f};
    float4 s = {0.f, 0.f, 0.f, 0.f};
    float4 q = {0.f, 0.f, 0.f, 0.f};
    const __half* src = g_Wx + ((size_t)b * Tt + (size_t)k * LCHUNK) * HH + h4;
#pragma unroll 10
    for (int t = 0; t < LCHUNK; t++) {
        float4 w = h4_to_f4(*(const uint2*)(src + (size_t)t * HH));
        s.x += w.x; s.y += w.y; s.z += w.z; s.w += w.w;
        q.x = fmaf(w.x, w.x, q.x); q.y = fmaf(w.y, w.y, q.y);
        q.z = fmaf(w.z, w.z, q.z); q.w = fmaf(w.w, w.w, q.w);
        ut.x = fmaf(a.x, ut.x, oma.x * w.x);
        ut.y = fmaf(a.y, ut.y, oma.y * w.y);
        ut.z = fmaf(a.z, ut.z, oma.z * w.z);
        ut.w = fmaf(a.w, ut.w, oma.w * w.w);
    }
    const size_t idx = (size_t)(k * Bb + b) * HH + h4;
    *(float4*)(g_chunkend + idx) = ut;
    *(float4*)(g_part_sum + idx) = s;
    *(float4*)(g_part_sq + idx) = q;
}

// ---------------- Stats reduce: 1280 -> 160 --------------------------------
__global__ void stats_reduce()
{
    const int h = threadIdx.x;
    const int p0 = blockIdx.x * 8;
    float s = 0.f, q = 0.f;
#pragma unroll
    for (int i = 0; i < 8; i++) {
        s += g_part_sum[(size_t)(p0 + i) * HH + h];
        q += g_part_sq[(size_t)(p0 + i) * HH + h];
    }
    g_red_sum[blockIdx.x * HH + h] = s;
    g_red_sq[blockIdx.x * HH + h] = q;
}

// ---------------- BN params ------------------------------------------------
__global__ void bn_params(const float* __restrict__ alpha,
                          const float* __restrict__ gamma,
                          const float* __restrict__ beta)
{
    const int h = threadIdx.x;
    float s = 0.f, q = 0.f;
#pragma unroll 8
    for (int p = 0; p < NRED; p++) {
        s += g_red_sum[p * HH + h];
        q += g_red_sq[p * HH + h];
    }
    const float invN = 1.0f / (float)MM;
    float mean = s * invN;
    float var = q * invN - mean * mean;
    float rs = rsqrtf(var + BN_EPS);
    float gg = gamma[h] * rs;
    float cc = beta[h] - mean * gg;
    float a = fminf(fmaxf(alpha[h], ALPHA_LO), ALPHA_HI);
    float aL = 1.0f;
    for (int i = 0; i < LCHUNK; i++) aL *= a;
    g_pa[h] = a;
    g_poma[h] = 1.0f - a;
    g_pg[h] = gg;
    g_pc[h] = cc;
    g_paL[h] = aL;
}

// ---------------- Combine: propagate BN-corrected chunk-start states -------
__global__ void combine_carries(const float* __restrict__ ut0)
{
    const int b = blockIdx.x, h = threadIdx.x;
    const float aL = g_paL[h];
    const float gg = g_pg[h];
    const float ccS = g_pc[h] * (1.0f - aL);
    float s = ut0[b * HH + h];
    g_start[(size_t)b * HH + h] = s;
#pragma unroll 13
    for (int k = 0; k < NCHUNK - 1; k++) {
        float endv = fmaf(gg, g_chunkend[((size_t)k * Bb + b) * HH + h], ccS);
        s = fmaf(aL, s, endv);
        g_start[((size_t)(k + 1) * Bb + b) * HH + h] = s;
    }
}

// ---------------- Scan: exact recurrence + softmax accumulation ------------
__global__ __launch_bounds__(128)
void scan_softmax()
{
    __shared__ float ssum[2][4];
    const int k = blockIdx.x, b = blockIdx.y, tid = threadIdx.x;
    const int lane = tid & 31, wid = tid >> 5;
    const int h4 = tid * 4;
    float4 a   = *(const float4*)(g_pa + h4);
    float4 oma = *(const float4*)(g_poma + h4);
    float4 gg  = *(const float4*)(g_pg + h4);
    float4 cc  = *(const float4*)(g_pc + h4);
    float4 ut  = *(const float4*)(g_start + ((size_t)k * Bb + b) * HH + h4);
    float4 acc = {0.f, 0.f, 0.f, 0.f};
    const __half* src = g_Wx + ((size_t)b * Tt + (size_t)k * LCHUNK) * HH + h4;

    uint2 wu = *(const uint2*)(src);
    for (int t = 0; t < LCHUNK; t++) {
        uint2 wn = make_uint2(0u, 0u);
        if (t + 1 < LCHUNK) wn = *(const uint2*)(src + (size_t)(t + 1) * HH);
        float4 w = h4_to_f4(wu);

        float w0 = fmaf(gg.x, w.x, cc.x);
        float w1 = fmaf(gg.y, w.y, cc.y);
        float w2 = fmaf(gg.z, w.z, cc.z);
        float w3 = fmaf(gg.w, w.w, cc.w);
        ut.x = fmaf(a.x, ut.x, oma.x * w0);
        ut.y = fmaf(a.y, ut.y, oma.y * w1);
        ut.z = fmaf(a.z, ut.z, oma.z * w2);
        ut.w = fmaf(a.w, ut.w, oma.w * w3);

        float e0 = __expf(ut.x);
        float e1 = __expf(ut.y);
        float e2 = __expf(ut.z);
        float e3 = __expf(ut.w);
        float sv = (e0 + e1) + (e2 + e3);
#pragma unroll
        for (int o = 16; o; o >>= 1) sv += __shfl_xor_sync(0xffffffffu, sv, o);
        if (lane == 0) ssum[t & 1][wid] = sv;
        __syncthreads();
        float inv = 1.0f / ((ssum[t & 1][0] + ssum[t & 1][1]) +
                            (ssum[t & 1][2] + ssum[t & 1][3]));

        acc.x = fmaf(e0, inv, acc.x);
        acc.y = fmaf(e1, inv, acc.y);
        acc.z = fmaf(e2, inv, acc.z);
        acc.w = fmaf(e3, inv, acc.w);
        wu = wn;
    }
    *(float4*)(g_accpart + ((size_t)k * Bb + b) * HH + h4) = acc;
}

// ---------------- Final deterministic reduction over chunks ----------------
__global__ void final_sum(float* __restrict__ out)
{
    const int b = blockIdx.x, h = threadIdx.x;
    float s = 0.f;
#pragma unroll 8
    for (int k = 0; k < NCHUNK; k++)
        s += g_accpart[((size_t)k * Bb + b) * HH + h];
    out[b * HH + h] = s;
}

// ---------------- launch ---------------------------------------------------
typedef CUresult (*EncodeTiledFn)(
    CUtensorMap*, CUtensorMapDataType, cuuint32_t, void*,
    const cuuint64_t*, const cuuint64_t*, const cuuint32_t*, const cuuint32_t*,
    CUtensorMapInterleave, CUtensorMapSwizzle, CUtensorMapL2promotion,
    CUtensorMapFloatOOBfill);

extern "C" void kernel_launch(void* const* d_in, const int* in_sizes, int n_in,
                              void* d_out, int out_size)
{
    const float* x     = (const float*)d_in[0];
    const float* W     = (const float*)d_in[1];
    const float* bias  = (const float*)d_in[2];
    const float* alpha = (const float*)d_in[3];
    const float* gamma = (const float*)d_in[4];
    const float* beta  = (const float*)d_in[5];
    const float* ut0   = (const float*)d_in[6];
    float* out = (float*)d_out;

    cudaFuncSetAttribute(gemm_tc, cudaFuncAttributeMaxDynamicSharedMemorySize, SM_TOTAL);

    // Build TMA descriptors for g_Whi / g_Wlo (driver entry point; no -lcuda).
    void* whiAddr = nullptr; void* wloAddr = nullptr;
    cudaGetSymbolAddress(&whiAddr, g_Whi);
    cudaGetSymbolAddress(&wloAddr, g_Wlo);
    void* fp = nullptr;
    cudaDriverEntryPointQueryResult qres;
    cudaGetDriverEntryPoint("cuTensorMapEncodeTiled", &fp, cudaEnableDefault, &qres);
    EncodeTiledFn enc = (EncodeTiledFn)fp;
    CUtensorMap mapHi{}, mapLo{};
    cuuint64_t dims[3]    = {DIN, HH, 1};
    cuuint64_t strides[2] = {DIN * 2, (cuuint64_t)DIN * HH * 2};
    cuuint32_t box[3]     = {64, 128, 1};     // 128B inner (SW128 limit) x 128 rows
    cuuint32_t est[3]     = {1, 1, 1};
    enc(&mapHi, CU_TENSOR_MAP_DATA_TYPE_BFLOAT16, 3, whiAddr, dims, strides, box, est,
        CU_TENSOR_MAP_INTERLEAVE_NONE, CU_TENSOR_MAP_SWIZZLE_128B,
        CU_TENSOR_MAP_L2_PROMOTION_L2_128B, CU_TENSOR_MAP_FLOAT_OOB_FILL_NONE);
    enc(&mapLo, CU_TENSOR_MAP_DATA_TYPE_BFLOAT16, 3, wloAddr, dims, strides, box, est,
        CU_TENSOR_MAP_INTERLEAVE_NONE, CU_TENSOR_MAP_SWIZZLE_128B,
        CU_TENSOR_MAP_L2_PROMOTION_L2_128B, CU_TENSOR_MAP_FLOAT_OOB_FILL_NONE);

    convert_W<<<(HH * DIN) / (256 * 4), 256>>>(W);
    dummy_k<<<1, 32>>>();      // launch-index padding: keeps gemm_tc at ncu's
    dummy_k<<<1, 32>>>();      // capture slot (-s 5 -c 1)
    gemm_tc<<<MM / 64, 320, SM_TOTAL>>>(x, bias, mapHi, mapLo);
    carry_stats<<<dim3(NCHUNK, Bb), 128>>>(alpha);
    stats_reduce<<<NRED, HH>>>();
    bn_params<<<1, HH>>>(alpha, gamma, beta);
    combine_carries<<<Bb, HH>>>(ut0);
    scan_softmax<<<dim3(NCHUNK, Bb), 128>>>();
    final_sum<<<Bb, HH>>>(out);
}

// round 16
// speedup vs baseline: 1.1873x; 1.1873x over previous
#include <cuda_runtime.h>
#include <cuda_bf16.h>
#include <cuda_fp16.h>
#include <cstdint>

// Problem constants
#define Bb 32
#define Tt 2000
#define DIN 512
#define HH 512
#define MM (Bb * Tt)            // 64000 rows
#define NCHUNK 40
#define LCHUNK 50               // Tt / NCHUNK
#define NSTAT (NCHUNK * Bb)     // 1280 stats partials
#define NRED 160                // second-level stats partials

#define ALPHA_LO 0.8187307530779818f   // exp(-1/5)
#define ALPHA_HI 0.9607894391523232f   // exp(-1/25)
#define BN_EPS 1e-5f

// tcgen05 is only legal on the arch-specific (sm_103a) compilation pass.
#if defined(__CUDA_ARCH__) && (defined(__CUDA_ARCH_FEAT_SM103_ALL) || \
    defined(__CUDA_ARCH_FEAT_SM100_ALL) || defined(__CUDA_ARCH_SPECIFIC__) || \
    defined(__CUDA_ARCH_FAMILY_SPECIFIC__))
#define TC_OK 1
#else
#define TC_OK 0
#endif

// ---------------- scratch (device globals; no allocation allowed) ----------
__device__ __align__(16) __half g_Wx[(size_t)MM * HH];  // 65.5 MB (fp16)
__device__ __align__(16) __nv_bfloat16 g_Whi[(size_t)HH * DIN];
__device__ __align__(16) __nv_bfloat16 g_Wlo[(size_t)HH * DIN];
__device__ float g_part_sum[NSTAT * HH];
__device__ float g_part_sq[NSTAT * HH];
__device__ float g_red_sum[NRED * HH];
__device__ float g_red_sq[NRED * HH];
__device__ float g_pa[HH], g_poma[HH], g_pg[HH], g_pc[HH], g_paL[HH];
__device__ float g_chunkend[(size_t)NCHUNK * Bb * HH];   // RAW (pre-BN) endpoints
__device__ float g_start[(size_t)NCHUNK * Bb * HH];
__device__ float g_accpart[(size_t)NCHUNK * Bb * HH];

// ======================= PTX helpers (arch-guarded) ========================
__device__ __forceinline__ uint32_t smem_u32(const void* p) {
    uint32_t a;
    asm("{ .reg .u64 t; cvta.to.shared.u64 t, %1; cvt.u32.u64 %0, t; }" : "=r"(a) : "l"(p));
    return a;
}
__device__ __forceinline__ uint32_t elect_one() {
    uint32_t pred;
    asm volatile("{\n\t.reg .pred p;\n\telect.sync _|p, 0xFFFFFFFF;\n\tselp.b32 %0, 1, 0, p;\n\t}" : "=r"(pred));
    return pred;
}
__device__ __forceinline__ uint32_t cl_rank() {
    uint32_t r;
    asm("mov.u32 %0, %%cluster_ctarank;" : "=r"(r));
    return r;
}
__device__ __forceinline__ void cluster_sync() {
    asm volatile("barrier.cluster.arrive.aligned;" ::: "memory");
    asm volatile("barrier.cluster.wait.aligned;" ::: "memory");
}
__device__ __forceinline__ void mbar_init(uint32_t a, uint32_t n) {
    asm volatile("mbarrier.init.shared.b64 [%0], %1;" :: "r"(a), "r"(n) : "memory");
}
__device__ __forceinline__ void mbar_arrive_local(uint32_t a) {
    asm volatile("mbarrier.arrive.shared.b64 _, [%0];" :: "r"(a) : "memory");
}
// local wait (acquire cta)
__device__ __forceinline__ void mbar_wait(uint32_t a, uint32_t parity) {
    asm volatile(
        "{\n\t.reg .pred P;\n\t"
        "LW%=:\n\t"
        "mbarrier.try_wait.parity.acquire.cta.shared::cta.b64 P, [%0], %1, 0x989680;\n\t"
        "@P bra LD%=;\n\t"
        "bra LW%=;\n\t"
        "LD%=:\n\t}"
        :: "r"(a), "r"(parity) : "memory");
}
// cluster-scope acquire wait (leader consuming peer arrivals)
__device__ __forceinline__ void mbar_wait_cl(uint32_t a, uint32_t parity) {
    asm volatile(
        "{\n\t.reg .pred P;\n\t"
        "LW%=:\n\t"
        "mbarrier.try_wait.parity.acquire.cluster.shared::cta.b64 P, [%0], %1, 0x989680;\n\t"
        "@P bra LD%=;\n\t"
        "bra LW%=;\n\t"
        "LD%=:\n\t}"
        :: "r"(a), "r"(parity) : "memory");
}
// arrive (release, cluster scope) on target-rank CTA's mbarrier at same offset
__device__ __forceinline__ void mbar_arrive_rank(uint32_t local_mbar, uint32_t tgt) {
    asm volatile(
        "{\n\t.reg .b32 ra;\n\t"
        "mapa.shared::cluster.u32 ra, %0, %1;\n\t"
        "mbarrier.arrive.release.cluster.shared::cluster.b64 _, [ra];\n\t}"
        :: "r"(local_mbar), "r"(tgt) : "memory");
}
__device__ __forceinline__ void tc_alloc_cg2(uint32_t smem_addr, uint32_t ncols) {
#if TC_OK
    asm volatile("tcgen05.alloc.cta_group::2.sync.aligned.shared::cta.b32 [%0], %1;"
                 :: "r"(smem_addr), "r"(ncols) : "memory");
#endif
}
__device__ __forceinline__ void tc_relinq_cg2() {
#if TC_OK
    asm volatile("tcgen05.relinquish_alloc_permit.cta_group::2.sync.aligned;");
#endif
}
__device__ __forceinline__ void tc_dealloc_cg2(uint32_t tmem, uint32_t ncols) {
#if TC_OK
    asm volatile("tcgen05.dealloc.cta_group::2.sync.aligned.b32 %0, %1;" :: "r"(tmem), "r"(ncols));
#endif
}
__device__ __forceinline__ void tc_commit_mc2(uint32_t mbar, uint16_t mask) {
#if TC_OK
    asm volatile(
        "tcgen05.commit.cta_group::2.mbarrier::arrive::one.shared::cluster.multicast::cluster.b64 [%0], %1;"
        :: "r"(mbar), "h"(mask) : "memory");
#endif
}
__device__ __forceinline__ void fence_async_smem() {
    asm volatile("fence.proxy.async.shared::cta;" ::: "memory");
}
__device__ __forceinline__ void tc_fence_after() {
#if TC_OK
    asm volatile("tcgen05.fence::after_thread_sync;" ::: "memory");
#endif
}
__device__ __forceinline__ void tc_wait_ld() {
#if TC_OK
    asm volatile("tcgen05.wait::ld.sync.aligned;" ::: "memory");
#endif
}
// cg2 bf16 SS MMA (M=256 across the pair)
__device__ __forceinline__ void mma_f16_ss_cg2(uint32_t d, uint64_t ad, uint64_t bd,
                                               uint32_t idesc, uint32_t en) {
#if TC_OK
    asm volatile(
        "{\n\t.reg .pred p;\n\tsetp.ne.u32 p, %5, 0;\n\t"
        "tcgen05.mma.cta_group::2.kind::f16 [%0], %1, %2, %3, {%4,%4,%4,%4,%4,%4,%4,%4}, p;\n\t}"
        :: "r"(d), "l"(ad), "l"(bd), "r"(idesc), "r"(0u), "r"(en) : "memory");
#endif
}
__device__ __forceinline__ void ldtm_x32(uint32_t* r, uint32_t addr) {
#if TC_OK
    asm volatile(
        "tcgen05.ld.sync.aligned.32x32b.x32.b32 "
        "{%0, %1, %2, %3, %4, %5, %6, %7, %8, %9, %10, %11, %12, %13, %14, %15, "
        " %16, %17, %18, %19, %20, %21, %22, %23, %24, %25, %26, %27, %28, %29, %30, %31}, [%32];"
        : "=r"(r[0]), "=r"(r[1]), "=r"(r[2]), "=r"(r[3]), "=r"(r[4]), "=r"(r[5]), "=r"(r[6]), "=r"(r[7]),
          "=r"(r[8]), "=r"(r[9]), "=r"(r[10]), "=r"(r[11]), "=r"(r[12]), "=r"(r[13]), "=r"(r[14]), "=r"(r[15]),
          "=r"(r[16]), "=r"(r[17]), "=r"(r[18]), "=r"(r[19]), "=r"(r[20]), "=r"(r[21]), "=r"(r[22]), "=r"(r[23]),
          "=r"(r[24]), "=r"(r[25]), "=r"(r[26]), "=r"(r[27]), "=r"(r[28]), "=r"(r[29]), "=r"(r[30]), "=r"(r[31])
        : "r"(addr));
#else
    for (int i = 0; i < 32; i++) r[i] = 0u;
#endif
}
#define SMEM_DESC_BASE_SW128 \
    ((uint64_t(2) << 61) | (uint64_t(1) << 46) | (uint64_t(64) << 32) | (uint64_t(1) << 16))
__device__ __forceinline__ uint64_t make_desc(uint32_t addr) {
    return SMEM_DESC_BASE_SW128 | ((uint64_t)(addr >> 4) & 0x3FFF);
}

// fp32 pair -> packed bf16x2 hi, residual packed bf16x2 lo
__device__ __forceinline__ uint32_t bf2_hi_lo(float a, float b, uint32_t& lo) {
    uint32_t hi;
    asm("cvt.rn.bf16x2.f32 %0, %1, %2;" : "=r"(hi) : "f"(b), "f"(a));
    __nv_bfloat162 h = *(__nv_bfloat162*)&hi;
    float ra = a - __bfloat162float(h.x);
    float rb = b - __bfloat162float(h.y);
    asm("cvt.rn.bf16x2.f32 %0, %1, %2;" : "=r"(lo) : "f"(rb), "f"(ra));
    return hi;
}
// 4 halves -> float4
__device__ __forceinline__ float4 h4_to_f4(uint2 v) {
    float2 f01 = __half22float2(*(__half2*)&v.x);
    float2 f23 = __half22float2(*(__half2*)&v.y);
    return make_float4(f01.x, f01.y, f23.x, f23.y);
}

// ---------------- dummy (ncu launch-index alignment) -----------------------
__global__ void dummy_k() {}

// ---------------- W -> bf16 hi/lo (tiny, once) -----------------------------
__global__ void convert_W(const float* __restrict__ W) {
    size_t i = ((size_t)blockIdx.x * 256 + threadIdx.x) * 4;
    float4 v = *(const float4*)(W + i);
    uint32_t l01, l23;
    uint32_t h01 = bf2_hi_lo(v.x, v.y, l01);
    uint32_t h23 = bf2_hi_lo(v.z, v.w, l23);
    *(uint2*)((uint16_t*)g_Whi + i) = make_uint2(h01, h23);
    *(uint2*)((uint16_t*)g_Wlo + i) = make_uint2(l01, l23);
}

// ======================= tcgen05 cg2 GEMM, 2 clusters/SM ===================
// Cluster of 2 CTAs = one M=256 x N=256 tile; TMEM 256 cols/CTA so TWO
// clusters co-reside per SM pair. Grid 1000 CTAs = 500 clusters.
// Per chunk j (K=64): sub0 = {Ahi,Alo} x Bhi, sub1 = Ahi x Blo.
// Critical-path fix: loaders prefetch next chunk's B-hi into REGISTERS while
// MMAs run; at BE0-flip only an STS+publish remains (no exposed LDG).
// A has its own AF barrier (2-chunk slack). B-lo stays direct LDG (covered
// by sub0's MMA shadow).
#define BK 64
// smem barrier offsets
#define SM_AE 8u                 // A_empty[2]
#define SM_AF 24u                // A_full[2]  (count 2, cluster arrivals)
#define SM_BE0 40u               // B-hi empty
#define SM_BE1 48u               // B-lo empty
#define SM_BF0 56u               // B-hi full (count 2)
#define SM_BF1 64u               // B-lo full (count 2)
#define SM_DONE 72u
#define SM_A0 1024u
#define SM_A1 33792u
#define SM_B0 66560u
#define SM_B1 82944u
#define SM_TOTAL 99328
// idesc: dtype=F32, atype=BF16, btype=BF16, N=256, M=256 (cg2)
#define GEMM_IDESC ((1u << 4) | (1u << 7) | (1u << 10) | (32u << 17) | (16u << 24))

__global__ __launch_bounds__(288, 2) __cluster_dims__(2, 1, 1)
void gemm_tc(const float* __restrict__ xa, const float* __restrict__ bias)
{
    extern __shared__ char smem[];
    const uint32_t sb = smem_u32(smem);
    const int tid = threadIdx.x;
    const int wid = tid >> 5;
    const int lid = tid & 31;
    const uint32_t rank = cl_rank();
    const int clus = blockIdx.x >> 1;
    const int N0 = (clus & 1) * 256;                     // cluster's N half
    const int mA = (clus >> 1) * 256 + (int)rank * 128;  // this CTA's 128 A rows
    const int nB = N0 + (int)rank * 128;                 // this CTA's 128 B rows

    if (wid == 8) {
        tc_alloc_cg2(sb + 0, 256);
        tc_relinq_cg2();
    }
    if (tid == 0) {
        for (int s = 0; s < 2; s++) { mbar_init(sb + SM_AE + s * 8, 1); mbar_arrive_local(sb + SM_AE + s * 8); }
        for (int s = 0; s < 2; s++) { mbar_init(sb + SM_AF + s * 8, 2); }
        mbar_init(sb + SM_BE0, 1); mbar_arrive_local(sb + SM_BE0);
        mbar_init(sb + SM_BE1, 1); mbar_arrive_local(sb + SM_BE1);
        mbar_init(sb + SM_BF0, 2);
        mbar_init(sb + SM_BF1, 2);
        mbar_init(sb + SM_DONE, 1);
    }
    __syncthreads();
    cluster_sync();                   // barriers visible cluster-wide
    uint32_t tbase;
    asm volatile("ld.shared.b32 %0, [%1];" : "=r"(tbase) : "r"(sb + 0));

    // A loader: own 128 rows x 64 cols fp32 -> hi(16K)+lo(16K) SW128
    auto load_a = [&](int k0, char* abuf) {
#pragma unroll
        for (int i2 = 0; i2 < 4; i2++) {
            int idx = i2 * 256 + tid;           // 0..1023
            int row = idx >> 3, u = idx & 7;
            const float* s = xa + (size_t)(mA + row) * DIN + k0 + u * 8;
            float4 f0 = *(const float4*)s;
            float4 f1 = *(const float4*)(s + 4);
            uint32_t l0, l1, l2, l3;
            uint4 hv;
            hv.x = bf2_hi_lo(f0.x, f0.y, l0);
            hv.y = bf2_hi_lo(f0.z, f0.w, l1);
            hv.z = bf2_hi_lo(f1.x, f1.y, l2);
            hv.w = bf2_hi_lo(f1.z, f1.w, l3);
            int off = row * 128 + ((u ^ (row & 7)) * 16);
            *(uint4*)(abuf + off) = hv;
            *(uint4*)(abuf + off + 16384) = make_uint4(l0, l1, l2, l3);
        }
    };
    // B-lo loader: own 128 N-rows x 64 cols bf16, SW128 (16KB), direct
    auto load_b_lo = [&](int k0, char* bbuf) {
#pragma unroll
        for (int i2 = 0; i2 < 4; i2++) {
            int idx = i2 * 256 + tid;
            int row = idx >> 3, u = idx & 7;
            uint4 v = *(const uint4*)(g_Wlo + (size_t)(nB + row) * DIN + k0 + u * 8);
            *(uint4*)(bbuf + row * 128 + ((u ^ (row & 7)) * 16)) = v;
        }
    };

    if (tid < 256) {
        // ---- loader warps with B-hi register prefetch ----
        uint4 pbh[4];
        auto prefetch_bh = [&](int k0) {
#pragma unroll
            for (int i2 = 0; i2 < 4; i2++) {
                int idx = i2 * 256 + tid;
                int row = idx >> 3, u = idx & 7;
                pbh[i2] = *(const uint4*)(g_Whi + (size_t)(nB + row) * DIN + k0 + u * 8);
            }
        };
        auto sts_bh = [&](char* bbuf) {
#pragma unroll
            for (int i2 = 0; i2 < 4; i2++) {
                int idx = i2 * 256 + tid;
                int row = idx >> 3, u = idx & 7;
                *(uint4*)(bbuf + row * 128 + ((u ^ (row & 7)) * 16)) = pbh[i2];
            }
        };
        prefetch_bh(0);
        for (int j = 0; j < 8; j++) {
#if TC_OK
            mbar_wait(sb + SM_AE + (j & 1) * 8, (j >> 1) & 1);
#endif
            load_a(j * BK, smem + ((j & 1) ? SM_A1 : SM_A0));
            fence_async_smem();
            asm volatile("bar.sync 1, 256;" ::: "memory");
            if (tid == 0) mbar_arrive_rank(sb + SM_AF + (j & 1) * 8, 0);
#if TC_OK
            mbar_wait(sb + SM_BE0, j & 1);
#endif
            sts_bh(smem + SM_B0);
            fence_async_smem();
            asm volatile("bar.sync 1, 256;" ::: "memory");
            if (tid == 0) mbar_arrive_rank(sb + SM_BF0, 0);
            if (j + 1 < 8) prefetch_bh((j + 1) * BK);
#if TC_OK
            mbar_wait(sb + SM_BE1, j & 1);
#endif
            load_b_lo(j * BK, smem + SM_B1);
            fence_async_smem();
            asm volatile("bar.sync 1, 256;" ::: "memory");
            if (tid == 0) mbar_arrive_rank(sb + SM_BF1, 0);
        }
    } else if (rank == 0) {
        // ---- MMA warp (warp 8, leader CTA; one elected lane issues) ----
        if (elect_one()) {
            for (int j = 0; j < 8; j++) {
#if TC_OK
                mbar_wait_cl(sb + SM_AF + (j & 1) * 8, (j >> 1) & 1);
                mbar_wait_cl(sb + SM_BF0, j & 1);
#endif
                uint32_t abase = sb + ((j & 1) ? SM_A1 : SM_A0);
                uint64_t adh = make_desc(abase);
                uint64_t adl = make_desc(abase + 16384u);
                {
                    uint64_t bd = make_desc(sb + SM_B0);
#pragma unroll
                    for (int ks = 0; ks < 4; ks++) {
                        uint32_t en = (j == 0 && ks == 0) ? 0u : 1u;
                        mma_f16_ss_cg2(tbase, adh + ks * 2, bd + ks * 2, GEMM_IDESC, en);
                        mma_f16_ss_cg2(tbase, adl + ks * 2, bd + ks * 2, GEMM_IDESC, 1u);
                    }
                    tc_commit_mc2(sb + SM_BE0, 0x3);
                }
#if TC_OK
                mbar_wait_cl(sb + SM_BF1, j & 1);
#endif
                {
                    uint64_t bd = make_desc(sb + SM_B1);
#pragma unroll
                    for (int ks = 0; ks < 4; ks++)
                        mma_f16_ss_cg2(tbase, adh + ks * 2, bd + ks * 2, GEMM_IDESC, 1u);
                    tc_commit_mc2(sb + SM_BE1, 0x3);
                    tc_commit_mc2(sb + SM_AE + (j & 1) * 8, 0x3);
                }
            }
            tc_commit_mc2(sb + SM_DONE, 0x3);   // all MMAs complete -> DONE
        }
    }

    // ---- drain: every thread waits DONE (multicast to both CTAs) ----
#if TC_OK
    mbar_wait(sb + SM_DONE, 0);
#endif
    __syncthreads();
    tc_fence_after();

    // epilogue: each CTA reads its own 128 TMEM lanes x 256 cols -> fp16 out
    if (wid < 8) {
        const int half = wid >> 2;             // col half
        const int m = mA + (wid & 3) * 32 + lid;
        __half* dst = g_Wx + (size_t)m * HH + N0 + half * 128;
#pragma unroll 1
        for (int c0 = 0; c0 < 128; c0 += 32) {
            uint32_t r[32];
            ldtm_x32(r, tbase + half * 128 + c0);
            tc_wait_ld();
#pragma unroll
            for (int jj = 0; jj < 32; jj += 8) {
                float4 bv0 = *(const float4*)(bias + N0 + half * 128 + c0 + jj);
                float4 bv1 = *(const float4*)(bias + N0 + half * 128 + c0 + jj + 4);
                __half2 h0 = __floats2half2_rn(__uint_as_float(r[jj + 0]) + bv0.x,
                                               __uint_as_float(r[jj + 1]) + bv0.y);
                __half2 h1 = __floats2half2_rn(__uint_as_float(r[jj + 2]) + bv0.z,
                                               __uint_as_float(r[jj + 3]) + bv0.w);
                __half2 h2 = __floats2half2_rn(__uint_as_float(r[jj + 4]) + bv1.x,
                                               __uint_as_float(r[jj + 5]) + bv1.y);
                __half2 h3 = __floats2half2_rn(__uint_as_float(r[jj + 6]) + bv1.z,
                                               __uint_as_float(r[jj + 7]) + bv1.w);
                uint4 o;
                o.x = *(uint32_t*)&h0; o.y = *(uint32_t*)&h1;
                o.z = *(uint32_t*)&h2; o.w = *(uint32_t*)&h3;
                *(uint4*)(dst + c0 + jj) = o;
            }
        }
    }
    __syncthreads();
    if (wid == 8) {
        tc_dealloc_cg2(tbase, 256);
    }
    cluster_sync();         // no CTA exits while peer ops may be in flight
}

// ---------------- Fused: chunk carries (raw) + BN stat partials ------------
__global__ __launch_bounds__(128)
void carry_stats(const float* __restrict__ alpha)
{
    const int k = blockIdx.x, b = blockIdx.y, tid = threadIdx.x;
    const int h4 = tid * 4;
    float4 av = *(const float4*)(alpha + h4);
    float4 a;
    a.x = fminf(fmaxf(av.x, ALPHA_LO), ALPHA_HI);
    a.y = fminf(fmaxf(av.y, ALPHA_LO), ALPHA_HI);
    a.z = fminf(fmaxf(av.z, ALPHA_LO), ALPHA_HI);
    a.w = fminf(fmaxf(av.w, ALPHA_LO), ALPHA_HI);
    float4 oma = {1.f - a.x, 1.f - a.y, 1.f - a.z, 1.f - a.w};
    float4 ut = {0.f, 0.f, 0.f, 0.f};
    float4 s = {0.f, 0.f, 0.f, 0.f};
    float4 q = {0.f, 0.f, 0.f, 0.f};
    const __half* src = g_Wx + ((size_t)b * Tt + (size_t)k * LCHUNK) * HH + h4;
#pragma unroll 10
    for (int t = 0; t < LCHUNK; t++) {
        float4 w = h4_to_f4(*(const uint2*)(src + (size_t)t * HH));
        s.x += w.x; s.y += w.y; s.z += w.z; s.w += w.w;
        q.x = fmaf(w.x, w.x, q.x); q.y = fmaf(w.y, w.y, q.y);
        q.z = fmaf(w.z, w.z, q.z); q.w = fmaf(w.w, w.w, q.w);
        ut.x = fmaf(a.x, ut.x, oma.x * w.x);
        ut.y = fmaf(a.y, ut.y, oma.y * w.y);
        ut.z = fmaf(a.z, ut.z, oma.z * w.z);
        ut.w = fmaf(a.w, ut.w, oma.w * w.w);
    }
    const size_t idx = (size_t)(k * Bb + b) * HH + h4;
    *(float4*)(g_chunkend + idx) = ut;
    *(float4*)(g_part_sum + idx) = s;
    *(float4*)(g_part_sq + idx) = q;
}

// ---------------- Stats reduce: 1280 -> 160 --------------------------------
__global__ void stats_reduce()
{
    const int h = threadIdx.x;
    const int p0 = blockIdx.x * 8;
    float s = 0.f, q = 0.f;
#pragma unroll
    for (int i = 0; i < 8; i++) {
        s += g_part_sum[(size_t)(p0 + i) * HH + h];
        q += g_part_sq[(size_t)(p0 + i) * HH + h];
    }
    g_red_sum[blockIdx.x * HH + h] = s;
    g_red_sq[blockIdx.x * HH + h] = q;
}

// ---------------- BN params ------------------------------------------------
__global__ void bn_params(const float* __restrict__ alpha,
                          const float* __restrict__ gamma,
                          const float* __restrict__ beta)
{
    const int h = threadIdx.x;
    float s = 0.f, q = 0.f;
#pragma unroll 8
    for (int p = 0; p < NRED; p++) {
        s += g_red_sum[p * HH + h];
        q += g_red_sq[p * HH + h];
    }
    const float invN = 1.0f / (float)MM;
    float mean = s * invN;
    float var = q * invN - mean * mean;
    float rs = rsqrtf(var + BN_EPS);
    float gg = gamma[h] * rs;
    float cc = beta[h] - mean * gg;
    float a = fminf(fmaxf(alpha[h], ALPHA_LO), ALPHA_HI);
    float aL = 1.0f;
    for (int i = 0; i < LCHUNK; i++) aL *= a;
    g_pa[h] = a;
    g_poma[h] = 1.0f - a;
    g_pg[h] = gg;
    g_pc[h] = cc;
    g_paL[h] = aL;
}

// ---------------- Combine: propagate BN-corrected chunk-start states -------
__global__ void combine_carries(const float* __restrict__ ut0)
{
    const int b = blockIdx.x, h = threadIdx.x;
    const float aL = g_paL[h];
    const float gg = g_pg[h];
    const float ccS = g_pc[h] * (1.0f - aL);
    float s = ut0[b * HH + h];
    g_start[(size_t)b * HH + h] = s;
#pragma unroll 13
    for (int k = 0; k < NCHUNK - 1; k++) {
        float endv = fmaf(gg, g_chunkend[((size_t)k * Bb + b) * HH + h], ccS);
        s = fmaf(aL, s, endv);
        g_start[((size_t)(k + 1) * Bb + b) * HH + h] = s;
    }
}

// ---------------- Scan: exact recurrence + softmax accumulation ------------
__global__ __launch_bounds__(128)
void scan_softmax()
{
    __shared__ float ssum[2][4];
    const int k = blockIdx.x, b = blockIdx.y, tid = threadIdx.x;
    const int lane = tid & 31, wid = tid >> 5;
    const int h4 = tid * 4;
    float4 a   = *(const float4*)(g_pa + h4);
    float4 oma = *(const float4*)(g_poma + h4);
    float4 gg  = *(const float4*)(g_pg + h4);
    float4 cc  = *(const float4*)(g_pc + h4);
    float4 ut  = *(const float4*)(g_start + ((size_t)k * Bb + b) * HH + h4);
    float4 acc = {0.f, 0.f, 0.f, 0.f};
    const __half* src = g_Wx + ((size_t)b * Tt + (size_t)k * LCHUNK) * HH + h4;

    uint2 wu = *(const uint2*)(src);
    for (int t = 0; t < LCHUNK; t++) {
        uint2 wn = make_uint2(0u, 0u);
        if (t + 1 < LCHUNK) wn = *(const uint2*)(src + (size_t)(t + 1) * HH);
        float4 w = h4_to_f4(wu);

        float w0 = fmaf(gg.x, w.x, cc.x);
        float w1 = fmaf(gg.y, w.y, cc.y);
        float w2 = fmaf(gg.z, w.z, cc.z);
        float w3 = fmaf(gg.w, w.w, cc.w);
        ut.x = fmaf(a.x, ut.x, oma.x * w0);
        ut.y = fmaf(a.y, ut.y, oma.y * w1);
        ut.z = fmaf(a.z, ut.z, oma.z * w2);
        ut.w = fmaf(a.w, ut.w, oma.w * w3);

        float e0 = __expf(ut.x);
        float e1 = __expf(ut.y);
        float e2 = __expf(ut.z);
        float e3 = __expf(ut.w);
        float sv = (e0 + e1) + (e2 + e3);
#pragma unroll
        for (int o = 16; o; o >>= 1) sv += __shfl_xor_sync(0xffffffffu, sv, o);
        if (lane == 0) ssum[t & 1][wid] = sv;
        __syncthreads();
        float inv = 1.0f / ((ssum[t & 1][0] + ssum[t & 1][1]) +
                            (ssum[t & 1][2] + ssum[t & 1][3]));

        acc.x = fmaf(e0, inv, acc.x);
        acc.y = fmaf(e1, inv, acc.y);
        acc.z = fmaf(e2, inv, acc.z);
        acc.w = fmaf(e3, inv, acc.w);
        wu = wn;
    }
    *(float4*)(g_accpart + ((size_t)k * Bb + b) * HH + h4) = acc;
}

// ---------------- Final deterministic reduction over chunks ----------------
__global__ void final_sum(float* __restrict__ out)
{
    const int b = blockIdx.x, h = threadIdx.x;
    float s = 0.f;
#pragma unroll 8
    for (int k = 0; k < NCHUNK; k++)
        s += g_accpart[((size_t)k * Bb + b) * HH + h];
    out[b * HH + h] = s;
}

// ---------------- launch ---------------------------------------------------
extern "C" void kernel_launch(void* const* d_in, const int* in_sizes, int n_in,
                              void* d_out, int out_size)
{
    const float* x     = (const float*)d_in[0];
    const float* W     = (const float*)d_in[1];
    const float* bias  = (const float*)d_in[2];
    const float* alpha = (const float*)d_in[3];
    const float* gamma = (const float*)d_in[4];
    const float* beta  = (const float*)d_in[5];
    const float* ut0   = (const float*)d_in[6];
    float* out = (float*)d_out;

    cudaFuncSetAttribute(gemm_tc, cudaFuncAttributeMaxDynamicSharedMemorySize, SM_TOTAL);

    convert_W<<<(HH * DIN) / (256 * 4), 256>>>(W);
    dummy_k<<<1, 32>>>();      // launch-index padding: keeps gemm_tc at ncu's
    dummy_k<<<1, 32>>>();      // capture slot (-s 5 -c 1)
    gemm_tc<<<MM / 64, 288, SM_TOTAL>>>(x, bias);   // 1000 CTAs = 500 clusters
    carry_stats<<<dim3(NCHUNK, Bb), 128>>>(alpha);
    stats_reduce<<<NRED, HH>>>();
    bn_params<<<1, HH>>>(alpha, gamma, beta);
    combine_carries<<<Bb, HH>>>(ut0);
    scan_softmax<<<dim3(NCHUNK, Bb), 128>>>();
    final_sum<<<Bb, HH>>>(out);
}

// round 17
// speedup vs baseline: 1.5250x; 1.2845x over previous
#include <cuda_runtime.h>
#include <cuda_bf16.h>
#include <cuda_fp16.h>
#include <cstdint>

// Problem constants
#define Bb 32
#define Tt 2000
#define DIN 512
#define HH 512
#define MM (Bb * Tt)            // 64000 rows
#define NCHUNK 40
#define LCHUNK 50               // Tt / NCHUNK
#define NSTAT (NCHUNK * Bb)     // 1280 stats partials
#define NRED 160                // second-level stats partials

#define ALPHA_LO 0.8187307530779818f   // exp(-1/5)
#define ALPHA_HI 0.9607894391523232f   // exp(-1/25)
#define BN_EPS 1e-5f

// tcgen05 is only legal on the arch-specific (sm_103a) compilation pass.
#if defined(__CUDA_ARCH__) && (defined(__CUDA_ARCH_FEAT_SM103_ALL) || \
    defined(__CUDA_ARCH_FEAT_SM100_ALL) || defined(__CUDA_ARCH_SPECIFIC__) || \
    defined(__CUDA_ARCH_FAMILY_SPECIFIC__))
#define TC_OK 1
#else
#define TC_OK 0
#endif

// ---------------- scratch (device globals; no allocation allowed) ----------
__device__ __align__(16) __half g_Wx[(size_t)MM * HH];  // 65.5 MB (fp16)
__device__ __align__(16) __nv_bfloat16 g_Whi[(size_t)HH * DIN];
__device__ float g_part_sum[NSTAT * HH];
__device__ float g_part_sq[NSTAT * HH];
__device__ float g_red_sum[NRED * HH];
__device__ float g_red_sq[NRED * HH];
__device__ float g_pa[HH], g_poma[HH], g_pg[HH], g_pc[HH], g_paL[HH];
__device__ float g_chunkend[(size_t)NCHUNK * Bb * HH];   // RAW (pre-BN) endpoints
__device__ float g_start[(size_t)NCHUNK * Bb * HH];
__device__ float g_accpart[(size_t)NCHUNK * Bb * HH];

// ======================= PTX helpers (arch-guarded) ========================
__device__ __forceinline__ uint32_t smem_u32(const void* p) {
    uint32_t a;
    asm("{ .reg .u64 t; cvta.to.shared.u64 t, %1; cvt.u32.u64 %0, t; }" : "=r"(a) : "l"(p));
    return a;
}
__device__ __forceinline__ uint32_t elect_one() {
    uint32_t pred;
    asm volatile("{\n\t.reg .pred p;\n\telect.sync _|p, 0xFFFFFFFF;\n\tselp.b32 %0, 1, 0, p;\n\t}" : "=r"(pred));
    return pred;
}
__device__ __forceinline__ uint32_t cl_rank() {
    uint32_t r;
    asm("mov.u32 %0, %%cluster_ctarank;" : "=r"(r));
    return r;
}
__device__ __forceinline__ void cluster_sync() {
    asm volatile("barrier.cluster.arrive.aligned;" ::: "memory");
    asm volatile("barrier.cluster.wait.aligned;" ::: "memory");
}
__device__ __forceinline__ void mbar_init(uint32_t a, uint32_t n) {
    asm volatile("mbarrier.init.shared.b64 [%0], %1;" :: "r"(a), "r"(n) : "memory");
}
__device__ __forceinline__ void mbar_arrive_local(uint32_t a) {
    asm volatile("mbarrier.arrive.shared.b64 _, [%0];" :: "r"(a) : "memory");
}
// local wait (acquire cta)
__device__ __forceinline__ void mbar_wait(uint32_t a, uint32_t parity) {
    asm volatile(
        "{\n\t.reg .pred P;\n\t"
        "LW%=:\n\t"
        "mbarrier.try_wait.parity.acquire.cta.shared::cta.b64 P, [%0], %1, 0x989680;\n\t"
        "@P bra LD%=;\n\t"
        "bra LW%=;\n\t"
        "LD%=:\n\t}"
        :: "r"(a), "r"(parity) : "memory");
}
// cluster-scope acquire wait (leader consuming peer arrivals)
__device__ __forceinline__ void mbar_wait_cl(uint32_t a, uint32_t parity) {
    asm volatile(
        "{\n\t.reg .pred P;\n\t"
        "LW%=:\n\t"
        "mbarrier.try_wait.parity.acquire.cluster.shared::cta.b64 P, [%0], %1, 0x989680;\n\t"
        "@P bra LD%=;\n\t"
        "bra LW%=;\n\t"
        "LD%=:\n\t}"
        :: "r"(a), "r"(parity) : "memory");
}
// arrive (release, cluster scope) on target-rank CTA's mbarrier at same offset
__device__ __forceinline__ void mbar_arrive_rank(uint32_t local_mbar, uint32_t tgt) {
    asm volatile(
        "{\n\t.reg .b32 ra;\n\t"
        "mapa.shared::cluster.u32 ra, %0, %1;\n\t"
        "mbarrier.arrive.release.cluster.shared::cluster.b64 _, [ra];\n\t}"
        :: "r"(local_mbar), "r"(tgt) : "memory");
}
__device__ __forceinline__ void tc_alloc_cg2(uint32_t smem_addr, uint32_t ncols) {
#if TC_OK
    asm volatile("tcgen05.alloc.cta_group::2.sync.aligned.shared::cta.b32 [%0], %1;"
                 :: "r"(smem_addr), "r"(ncols) : "memory");
#endif
}
__device__ __forceinline__ void tc_relinq_cg2() {
#if TC_OK
    asm volatile("tcgen05.relinquish_alloc_permit.cta_group::2.sync.aligned;");
#endif
}
__device__ __forceinline__ void tc_dealloc_cg2(uint32_t tmem, uint32_t ncols) {
#if TC_OK
    asm volatile("tcgen05.dealloc.cta_group::2.sync.aligned.b32 %0, %1;" :: "r"(tmem), "r"(ncols));
#endif
}
__device__ __forceinline__ void tc_commit_mc2(uint32_t mbar, uint16_t mask) {
#if TC_OK
    asm volatile(
        "tcgen05.commit.cta_group::2.mbarrier::arrive::one.shared::cluster.multicast::cluster.b64 [%0], %1;"
        :: "r"(mbar), "h"(mask) : "memory");
#endif
}
__device__ __forceinline__ void fence_async_smem() {
    asm volatile("fence.proxy.async.shared::cta;" ::: "memory");
}
__device__ __forceinline__ void tc_fence_after() {
#if TC_OK
    asm volatile("tcgen05.fence::after_thread_sync;" ::: "memory");
#endif
}
__device__ __forceinline__ void tc_wait_ld() {
#if TC_OK
    asm volatile("tcgen05.wait::ld.sync.aligned;" ::: "memory");
#endif
}
// cg2 bf16 SS MMA (M=256 across the pair)
__device__ __forceinline__ void mma_f16_ss_cg2(uint32_t d, uint64_t ad, uint64_t bd,
                                               uint32_t idesc, uint32_t en) {
#if TC_OK
    asm volatile(
        "{\n\t.reg .pred p;\n\tsetp.ne.u32 p, %5, 0;\n\t"
        "tcgen05.mma.cta_group::2.kind::f16 [%0], %1, %2, %3, {%4,%4,%4,%4,%4,%4,%4,%4}, p;\n\t}"
        :: "r"(d), "l"(ad), "l"(bd), "r"(idesc), "r"(0u), "r"(en) : "memory");
#endif
}
__device__ __forceinline__ void ldtm_x32(uint32_t* r, uint32_t addr) {
#if TC_OK
    asm volatile(
        "tcgen05.ld.sync.aligned.32x32b.x32.b32 "
        "{%0, %1, %2, %3, %4, %5, %6, %7, %8, %9, %10, %11, %12, %13, %14, %15, "
        " %16, %17, %18, %19, %20, %21, %22, %23, %24, %25, %26, %27, %28, %29, %30, %31}, [%32];"
        : "=r"(r[0]), "=r"(r[1]), "=r"(r[2]), "=r"(r[3]), "=r"(r[4]), "=r"(r[5]), "=r"(r[6]), "=r"(r[7]),
          "=r"(r[8]), "=r"(r[9]), "=r"(r[10]), "=r"(r[11]), "=r"(r[12]), "=r"(r[13]), "=r"(r[14]), "=r"(r[15]),
          "=r"(r[16]), "=r"(r[17]), "=r"(r[18]), "=r"(r[19]), "=r"(r[20]), "=r"(r[21]), "=r"(r[22]), "=r"(r[23]),
          "=r"(r[24]), "=r"(r[25]), "=r"(r[26]), "=r"(r[27]), "=r"(r[28]), "=r"(r[29]), "=r"(r[30]), "=r"(r[31])
        : "r"(addr));
#else
    for (int i = 0; i < 32; i++) r[i] = 0u;
#endif
}
#define SMEM_DESC_BASE_SW128 \
    ((uint64_t(2) << 61) | (uint64_t(1) << 46) | (uint64_t(64) << 32) | (uint64_t(1) << 16))
__device__ __forceinline__ uint64_t make_desc(uint32_t addr) {
    return SMEM_DESC_BASE_SW128 | ((uint64_t)(addr >> 4) & 0x3FFF);
}

__device__ __forceinline__ uint32_t bf2_pack(float a, float b) {
    uint32_t r;
    asm("cvt.rn.bf16x2.f32 %0, %1, %2;" : "=r"(r) : "f"(b), "f"(a));
    return r;
}
// 4 halves -> float4
__device__ __forceinline__ float4 h4_to_f4(uint2 v) {
    float2 f01 = __half22float2(*(__half2*)&v.x);
    float2 f23 = __half22float2(*(__half2*)&v.y);
    return make_float4(f01.x, f01.y, f23.x, f23.y);
}

// ---------------- dummy (ncu launch-index alignment) -----------------------
__global__ void dummy_k() {}

// ---------------- W -> bf16 (tiny, once) -----------------------------------
__global__ void convert_W(const float* __restrict__ W) {
    size_t i = ((size_t)blockIdx.x * 256 + threadIdx.x) * 4;
    float4 v = *(const float4*)(W + i);
    uint32_t h01 = bf2_pack(v.x, v.y);
    uint32_t h23 = bf2_pack(v.z, v.w);
    *(uint2*)((uint16_t*)g_Whi + i) = make_uint2(h01, h23);
}

// ======================= tcgen05 cg2 GEMM, single-term bf16 ================
// Cluster of 2 CTAs = one M=256 x N=256 tile; TMEM 256 cols/CTA so TWO
// clusters co-reside per SM pair. Grid 1000 CTAs = 500 clusters.
// 8 K-chunks of 64; ONE stage per chunk = A-hi 16K + B-hi 16K (32K), double
// buffered. One publish + one commit per chunk (half of R14's handshakes).
// Error budget: bf16 quantization ~4e-3 abs on unit-std Wx; pipeline
// attenuation measured at ~100x (fp16-Wx experiment) -> final ~4e-5.
#define BK 64
// smem barrier offsets
#define SM_SE 8u                 // stage_empty[2] (pre-armed)
#define SM_SF 24u                // stage_full[2]  (count 2, cluster arrivals)
#define SM_DONE 40u
#define SM_S0 1024u
#define SM_S1 33792u             // 1024 + 32768
#define SM_TOTAL 66560           // 1024 + 2*32768
// idesc: dtype=F32, atype=BF16, btype=BF16, N=256, M=256 (cg2)
#define GEMM_IDESC ((1u << 4) | (1u << 7) | (1u << 10) | (32u << 17) | (16u << 24))

__global__ __launch_bounds__(288, 2) __cluster_dims__(2, 1, 1)
void gemm_tc(const float* __restrict__ xa, const float* __restrict__ bias)
{
    extern __shared__ char smem[];
    const uint32_t sb = smem_u32(smem);
    const int tid = threadIdx.x;
    const int wid = tid >> 5;
    const int lid = tid & 31;
    const uint32_t rank = cl_rank();
    const int clus = blockIdx.x >> 1;
    const int N0 = (clus & 1) * 256;                     // cluster's N half
    const int mA = (clus >> 1) * 256 + (int)rank * 128;  // this CTA's 128 A rows
    const int nB = N0 + (int)rank * 128;                 // this CTA's 128 B rows

    if (wid == 8) {
        tc_alloc_cg2(sb + 0, 256);
        tc_relinq_cg2();
    }
    if (tid == 0) {
        for (int s = 0; s < 2; s++) { mbar_init(sb + SM_SE + s * 8, 1); mbar_arrive_local(sb + SM_SE + s * 8); }
        for (int s = 0; s < 2; s++) { mbar_init(sb + SM_SF + s * 8, 2); }
        mbar_init(sb + SM_DONE, 1);
    }
    __syncthreads();
    cluster_sync();                   // barriers visible cluster-wide
    uint32_t tbase;
    asm volatile("ld.shared.b32 %0, [%1];" : "=r"(tbase) : "r"(sb + 0));

    if (tid < 256) {
        // ---- loader warps: one stage (A+B) per chunk, 2-chunk run-ahead ----
        for (int j = 0; j < 8; j++) {
            const int k0 = j * BK;
            char* st = smem + ((j & 1) ? SM_S1 : SM_S0);
#if TC_OK
            mbar_wait(sb + SM_SE + (j & 1) * 8, (j >> 1) & 1);
#endif
            // A: own 128 rows x 64 cols fp32 -> bf16, SW128 (16K)
#pragma unroll
            for (int i2 = 0; i2 < 4; i2++) {
                int idx = i2 * 256 + tid;           // 0..1023
                int row = idx >> 3, u = idx & 7;
                const float* s = xa + (size_t)(mA + row) * DIN + k0 + u * 8;
                float4 f0 = *(const float4*)s;
                float4 f1 = *(const float4*)(s + 4);
                uint4 hv;
                hv.x = bf2_pack(f0.x, f0.y);
                hv.y = bf2_pack(f0.z, f0.w);
                hv.z = bf2_pack(f1.x, f1.y);
                hv.w = bf2_pack(f1.z, f1.w);
                *(uint4*)(st + row * 128 + ((u ^ (row & 7)) * 16)) = hv;
            }
            // B: own 128 N-rows x 64 cols bf16, SW128 (16K at +16K)
#pragma unroll
            for (int i2 = 0; i2 < 4; i2++) {
                int idx = i2 * 256 + tid;
                int row = idx >> 3, u = idx & 7;
                uint4 v = *(const uint4*)(g_Whi + (size_t)(nB + row) * DIN + k0 + u * 8);
                *(uint4*)(st + 16384 + row * 128 + ((u ^ (row & 7)) * 16)) = v;
            }
            fence_async_smem();
            asm volatile("bar.sync 1, 256;" ::: "memory");
            if (tid == 0) mbar_arrive_rank(sb + SM_SF + (j & 1) * 8, 0);
        }
    } else if (rank == 0) {
        // ---- MMA warp (warp 8, leader CTA; one elected lane issues) ----
        if (elect_one()) {
            for (int j = 0; j < 8; j++) {
#if TC_OK
                mbar_wait_cl(sb + SM_SF + (j & 1) * 8, (j >> 1) & 1);
#endif
                uint32_t st = sb + ((j & 1) ? SM_S1 : SM_S0);
                uint64_t ad = make_desc(st);
                uint64_t bd = make_desc(st + 16384u);
#pragma unroll
                for (int ks = 0; ks < 4; ks++) {
                    uint32_t en = (j == 0 && ks == 0) ? 0u : 1u;
                    mma_f16_ss_cg2(tbase, ad + ks * 2, bd + ks * 2, GEMM_IDESC, en);
                }
                tc_commit_mc2(sb + SM_SE + (j & 1) * 8, 0x3);
            }
            tc_commit_mc2(sb + SM_DONE, 0x3);   // all MMAs complete -> DONE
        }
    }

    // ---- drain: every thread waits DONE (multicast to both CTAs) ----
#if TC_OK
    mbar_wait(sb + SM_DONE, 0);
#endif
    __syncthreads();
    tc_fence_after();

    // epilogue: each CTA reads its own 128 TMEM lanes x 256 cols -> fp16 out
    if (wid < 8) {
        const int half = wid >> 2;             // col half
        const int m = mA + (wid & 3) * 32 + lid;
        __half* dst = g_Wx + (size_t)m * HH + N0 + half * 128;
#pragma unroll 1
        for (int c0 = 0; c0 < 128; c0 += 32) {
            uint32_t r[32];
            ldtm_x32(r, tbase + half * 128 + c0);
            tc_wait_ld();
#pragma unroll
            for (int jj = 0; jj < 32; jj += 8) {
                float4 bv0 = *(const float4*)(bias + N0 + half * 128 + c0 + jj);
                float4 bv1 = *(const float4*)(bias + N0 + half * 128 + c0 + jj + 4);
                __half2 h0 = __floats2half2_rn(__uint_as_float(r[jj + 0]) + bv0.x,
                                               __uint_as_float(r[jj + 1]) + bv0.y);
                __half2 h1 = __floats2half2_rn(__uint_as_float(r[jj + 2]) + bv0.z,
                                               __uint_as_float(r[jj + 3]) + bv0.w);
                __half2 h2 = __floats2half2_rn(__uint_as_float(r[jj + 4]) + bv1.x,
                                               __uint_as_float(r[jj + 5]) + bv1.y);
                __half2 h3 = __floats2half2_rn(__uint_as_float(r[jj + 6]) + bv1.z,
                                               __uint_as_float(r[jj + 7]) + bv1.w);
                uint4 o;
                o.x = *(uint32_t*)&h0; o.y = *(uint32_t*)&h1;
                o.z = *(uint32_t*)&h2; o.w = *(uint32_t*)&h3;
                *(uint4*)(dst + c0 + jj) = o;
            }
        }
    }
    __syncthreads();
    if (wid == 8) {
        tc_dealloc_cg2(tbase, 256);
    }
    cluster_sync();         // no CTA exits while peer ops may be in flight
}

// ---------------- Fused: chunk carries (raw) + BN stat partials ------------
__global__ __launch_bounds__(128)
void carry_stats(const float* __restrict__ alpha)
{
    const int k = blockIdx.x, b = blockIdx.y, tid = threadIdx.x;
    const int h4 = tid * 4;
    float4 av = *(const float4*)(alpha + h4);
    float4 a;
    a.x = fminf(fmaxf(av.x, ALPHA_LO), ALPHA_HI);
    a.y = fminf(fmaxf(av.y, ALPHA_LO), ALPHA_HI);
    a.z = fminf(fmaxf(av.z, ALPHA_LO), ALPHA_HI);
    a.w = fminf(fmaxf(av.w, ALPHA_LO), ALPHA_HI);
    float4 oma = {1.f - a.x, 1.f - a.y, 1.f - a.z, 1.f - a.w};
    float4 ut = {0.f, 0.f, 0.f, 0.f};
    float4 s = {0.f, 0.f, 0.f, 0.f};
    float4 q = {0.f, 0.f, 0.f, 0.f};
    const __half* src = g_Wx + ((size_t)b * Tt + (size_t)k * LCHUNK) * HH + h4;
#pragma unroll 10
    for (int t = 0; t < LCHUNK; t++) {
        float4 w = h4_to_f4(*(const uint2*)(src + (size_t)t * HH));
        s.x += w.x; s.y += w.y; s.z += w.z; s.w += w.w;
        q.x = fmaf(w.x, w.x, q.x); q.y = fmaf(w.y, w.y, q.y);
        q.z = fmaf(w.z, w.z, q.z); q.w = fmaf(w.w, w.w, q.w);
        ut.x = fmaf(a.x, ut.x, oma.x * w.x);
        ut.y = fmaf(a.y, ut.y, oma.y * w.y);
        ut.z = fmaf(a.z, ut.z, oma.z * w.z);
        ut.w = fmaf(a.w, ut.w, oma.w * w.w);
    }
    const size_t idx = (size_t)(k * Bb + b) * HH + h4;
    *(float4*)(g_chunkend + idx) = ut;
    *(float4*)(g_part_sum + idx) = s;
    *(float4*)(g_part_sq + idx) = q;
}

// ---------------- Stats reduce: 1280 -> 160 --------------------------------
__global__ void stats_reduce()
{
    const int h = threadIdx.x;
    const int p0 = blockIdx.x * 8;
    float s = 0.f, q = 0.f;
#pragma unroll
    for (int i = 0; i < 8; i++) {
        s += g_part_sum[(size_t)(p0 + i) * HH + h];
        q += g_part_sq[(size_t)(p0 + i) * HH + h];
    }
    g_red_sum[blockIdx.x * HH + h] = s;
    g_red_sq[blockIdx.x * HH + h] = q;
}

// ---------------- BN params ------------------------------------------------
__global__ void bn_params(const float* __restrict__ alpha,
                          const float* __restrict__ gamma,
                          const float* __restrict__ beta)
{
    const int h = threadIdx.x;
    float s = 0.f, q = 0.f;
#pragma unroll 8
    for (int p = 0; p < NRED; p++) {
        s += g_red_sum[p * HH + h];
        q += g_red_sq[p * HH + h];
    }
    const float invN = 1.0f / (float)MM;
    float mean = s * invN;
    float var = q * invN - mean * mean;
    float rs = rsqrtf(var + BN_EPS);
    float gg = gamma[h] * rs;
    float cc = beta[h] - mean * gg;
    float a = fminf(fmaxf(alpha[h], ALPHA_LO), ALPHA_HI);
    float aL = 1.0f;
    for (int i = 0; i < LCHUNK; i++) aL *= a;
    g_pa[h] = a;
    g_poma[h] = 1.0f - a;
    g_pg[h] = gg;
    g_pc[h] = cc;
    g_paL[h] = aL;
}

// ---------------- Combine: propagate BN-corrected chunk-start states -------
__global__ void combine_carries(const float* __restrict__ ut0)
{
    const int b = blockIdx.x, h = threadIdx.x;
    const float aL = g_paL[h];
    const float gg = g_pg[h];
    const float ccS = g_pc[h] * (1.0f - aL);
    float s = ut0[b * HH + h];
    g_start[(size_t)b * HH + h] = s;
#pragma unroll 13
    for (int k = 0; k < NCHUNK - 1; k++) {
        float endv = fmaf(gg, g_chunkend[((size_t)k * Bb + b) * HH + h], ccS);
        s = fmaf(aL, s, endv);
        g_start[((size_t)(k + 1) * Bb + b) * HH + h] = s;
    }
}

// ---------------- Scan: exact recurrence + softmax accumulation ------------
__global__ __launch_bounds__(128)
void scan_softmax()
{
    __shared__ float ssum[2][4];
    const int k = blockIdx.x, b = blockIdx.y, tid = threadIdx.x;
    const int lane = tid & 31, wid = tid >> 5;
    const int h4 = tid * 4;
    float4 a   = *(const float4*)(g_pa + h4);
    float4 oma = *(const float4*)(g_poma + h4);
    float4 gg  = *(const float4*)(g_pg + h4);
    float4 cc  = *(const float4*)(g_pc + h4);
    float4 ut  = *(const float4*)(g_start + ((size_t)k * Bb + b) * HH + h4);
    float4 acc = {0.f, 0.f, 0.f, 0.f};
    const __half* src = g_Wx + ((size_t)b * Tt + (size_t)k * LCHUNK) * HH + h4;

    uint2 wu = *(const uint2*)(src);
    for (int t = 0; t < LCHUNK; t++) {
        uint2 wn = make_uint2(0u, 0u);
        if (t + 1 < LCHUNK) wn = *(const uint2*)(src + (size_t)(t + 1) * HH);
        float4 w = h4_to_f4(wu);

        float w0 = fmaf(gg.x, w.x, cc.x);
        float w1 = fmaf(gg.y, w.y, cc.y);
        float w2 = fmaf(gg.z, w.z, cc.z);
        float w3 = fmaf(gg.w, w.w, cc.w);
        ut.x = fmaf(a.x, ut.x, oma.x * w0);
        ut.y = fmaf(a.y, ut.y, oma.y * w1);
        ut.z = fmaf(a.z, ut.z, oma.z * w2);
        ut.w = fmaf(a.w, ut.w, oma.w * w3);

        float e0 = __expf(ut.x);
        float e1 = __expf(ut.y);
        float e2 = __expf(ut.z);
        float e3 = __expf(ut.w);
        float sv = (e0 + e1) + (e2 + e3);
#pragma unroll
        for (int o = 16; o; o >>= 1) sv += __shfl_xor_sync(0xffffffffu, sv, o);
        if (lane == 0) ssum[t & 1][wid] = sv;
        __syncthreads();
        float inv = 1.0f / ((ssum[t & 1][0] + ssum[t & 1][1]) +
                            (ssum[t & 1][2] + ssum[t & 1][3]));

        acc.x = fmaf(e0, inv, acc.x);
        acc.y = fmaf(e1, inv, acc.y);
        acc.z = fmaf(e2, inv, acc.z);
        acc.w = fmaf(e3, inv, acc.w);
        wu = wn;
    }
    *(float4*)(g_accpart + ((size_t)k * Bb + b) * HH + h4) = acc;
}

// ---------------- Final deterministic reduction over chunks ----------------
__global__ void final_sum(float* __restrict__ out)
{
    const int b = blockIdx.x, h = threadIdx.x;
    float s = 0.f;
#pragma unroll 8
    for (int k = 0; k < NCHUNK; k++)
        s += g_accpart[((size_t)k * Bb + b) * HH + h];
    out[b * HH + h] = s;
}

// ---------------- launch ---------------------------------------------------
extern "C" void kernel_launch(void* const* d_in, const int* in_sizes, int n_in,
                              void* d_out, int out_size)
{
    const float* x     = (const float*)d_in[0];
    const float* W     = (const float*)d_in[1];
    const float* bias  = (const float*)d_in[2];
    const float* alpha = (const float*)d_in[3];
    const float* gamma = (const float*)d_in[4];
    const float* beta  = (const float*)d_in[5];
    const float* ut0   = (const float*)d_in[6];
    float* out = (float*)d_out;

    cudaFuncSetAttribute(gemm_tc, cudaFuncAttributeMaxDynamicSharedMemorySize, SM_TOTAL);

    convert_W<<<(HH * DIN) / (256 * 4), 256>>>(W);
    dummy_k<<<1, 32>>>();      // launch-index padding: keeps gemm_tc at ncu's
    dummy_k<<<1, 32>>>();      // capture slot (-s 5 -c 1)
    gemm_tc<<<MM / 64, 288, SM_TOTAL>>>(x, bias);   // 1000 CTAs = 500 clusters
    carry_stats<<<dim3(NCHUNK, Bb), 128>>>(alpha);
    stats_reduce<<<NRED, HH>>>();
    bn_params<<<1, HH>>>(alpha, gamma, beta);
    combine_carries<<<Bb, HH>>>(ut0);
    scan_softmax<<<dim3(NCHUNK, Bb), 128>>>();
    final_sum<<<Bb, HH>>>(out);
}